// round 14
// baseline (speedup 1.0000x reference)
#include <cuda_runtime.h>

// DistMaps: out[b,g,r,c] = tanh(2*sqrt(min_p d2)) over 24 clicks per (b,g) group,
// d2 = ((r-pr)/5)^2 + ((c-pc)/5)^2, invalid clicks (max coords < 0) -> 1e6.
// x input (d_in[0]) is shape-only; output depends only on coords (d_in[1]).
//
// R14: R13 (best bench: regs=32, single wave, tolerance cull, branchless
// epilogue) + work DECLUSTERING. Previous mapping gave each CTA 8 contiguous
// row-band windows -> CTAs near a click band were all-active, most all-idle;
// per-SM time is gated by max-of-CTAs. New mapping scatters each CTA's 8
// warps across the image (wloc = wid*64 + bx), flattening the active-warp
// distribution per CTA (binomial instead of 0-or-8). Same instructions, same
// per-warp coalescing.
//
// Tolerance cull: writing 1.0f wherever min d2 >= 6.25 errs by 1-tanh(5) =
// 9.1e-5, 10x inside the 1e-3 harness tolerance (measured rel_err 4.3e-5).

namespace {

constexpr int   W         = 512;
constexpr int   P         = 24;      // clicks per group
constexpr float INV_SCALE = 0.2f;    // 1 / (NORM_RADIUS * SPATIAL_SCALE)
constexpr float CULL_D2   = 6.25f;   // 1 - tanh(2*sqrt(6.25)) = 9.1e-5

__device__ __forceinline__ float tanh_2sqrt_fast(float q) {
    float s, t;
    asm("sqrt.approx.f32 %0, %1;" : "=f"(s) : "f"(q));
    s = 2.0f * s;
    asm("tanh.approx.f32 %0, %1;" : "=f"(t) : "f"(s));
    return t;
}

__global__ __launch_bounds__(256, 8) void distmaps_kernel(
    const float* __restrict__ coords,   // [B, 48, 3] (row, col, _)
    float*       __restrict__ out)      // [B, 2, H, W]
{
    const int tid  = threadIdx.x;
    const int lane = tid & 31;
    const int bg   = blockIdx.y;                      // 0..2B-1

    // Declustered window mapping: CTA bx gets windows {bx, 64+bx, ..., 448+bx},
    // one per 64-row band -> active warps spread evenly over CTAs.
    const int wloc = ((tid >> 5) << 6) + blockIdx.x;  // 0..511 window in group
    const int r0   = (wloc >> 2) << 2;                // window row base (4 rows)
    const int c0   = (wloc & 3) << 7;                 // window col base (128)

    // Lane p holds click p; test click against this warp's 4x128 window.
    float prs = 0.0f, pcs = 0.0f;
    bool  nearp = false;
    if (lane < P) {
        const float* cp = coords + (bg * P + lane) * 3;
        const float pr = __ldg(cp);
        const float pc = __ldg(cp + 1);
        const bool valid = fmaxf(pr, pc) >= 0.0f;     // invalid iff both < 0
        const float rr = fminf(fmaxf(pr, (float)r0), (float)(r0 + 3));
        const float cc = fminf(fmaxf(pc, (float)c0), (float)(c0 + 127));
        const float dr = (rr - pr) * INV_SCALE;
        const float dc = (cc - pc) * INV_SCALE;
        nearp = valid && (fmaf(dr, dr, dc * dc) < CULL_D2);
        prs = pr * INV_SCALE;
        pcs = pc * INV_SCALE;
    }
    unsigned mask = __ballot_sync(0xffffffffu, nearp);

    // Output index: bg<<18 | r0<<9 | c0 | lane<<2 (disjoint bit fields).
    const unsigned idx = ((unsigned)bg << 18) | ((unsigned)r0 << 9) |
                         (unsigned)(c0 | (lane << 2));
    float* obase = out + idx;

    if (mask == 0u) {
        // No click within reach: all pixels -> 1.0f (err <= 9.1e-5).
        const float4 ones = make_float4(1.0f, 1.0f, 1.0f, 1.0f);
#pragma unroll
        for (int i = 0; i < 4; ++i)
            *reinterpret_cast<float4*>(obase + i * W) = ones;
        return;
    }

    const float a0  = (float)(c0 | (lane << 2)) * INV_SCALE;
    const float rs0 = (float)r0 * INV_SCALE;

    float q[4][4];
#pragma unroll
    for (int i = 0; i < 4; ++i)
#pragma unroll
        for (int j = 0; j < 4; ++j) q[i][j] = CULL_D2;

    // Iterate surviving clicks (warp-uniform mask -> no divergence).
    while (mask) {
        const int p = __ffs(mask) - 1;
        mask &= mask - 1;
        const float pr = __shfl_sync(0xffffffffu, prs, p);
        const float pc = __shfl_sync(0xffffffffu, pcs, p);

        // Incremental column/row deltas keep the live set small (reg cap 32).
        const float dc0 = a0 - pc;
        const float dc1 = dc0 + INV_SCALE;
        const float dc2 = dc1 + INV_SCALE;
        const float dc3 = dc2 + INV_SCALE;
        float dr = rs0 - pr;
#pragma unroll
        for (int i = 0; i < 4; ++i) {
            const float e = dr * dr;
            q[i][0] = fminf(q[i][0], fmaf(dc0, dc0, e));
            q[i][1] = fminf(q[i][1], fmaf(dc1, dc1, e));
            q[i][2] = fminf(q[i][2], fmaf(dc2, dc2, e));
            q[i][3] = fminf(q[i][3], fmaf(dc3, dc3, e));
            dr += INV_SCALE;
        }
    }

    // Branchless epilogue (no vote): active warps always run MUFU.
#pragma unroll
    for (int i = 0; i < 4; ++i) {
        float4 v;
        v.x = tanh_2sqrt_fast(q[i][0]);
        v.y = tanh_2sqrt_fast(q[i][1]);
        v.z = tanh_2sqrt_fast(q[i][2]);
        v.w = tanh_2sqrt_fast(q[i][3]);
        *reinterpret_cast<float4*>(obase + i * W) = v;
    }
}

}  // namespace

extern "C" void kernel_launch(void* const* d_in, const int* in_sizes, int n_in,
                              void* d_out, int out_size) {
    // d_in[0]: x [B,3,512,512] f32 (unused), d_in[1]: coords [B,48,3] f32
    const float* coords = (const float*)d_in[1];
    float* out = (float*)d_out;

    const int B = in_sizes[1] / (48 * 3);   // 8
    dim3 grid(64, B * 2);                   // 1024 CTAs -> single wave @ 8/SM
    distmaps_kernel<<<grid, 256>>>(coords, out);
}

// round 15
// speedup vs baseline: 1.0037x; 1.0037x over previous
#include <cuda_runtime.h>

// DistMaps: out[b,g,r,c] = tanh(2*sqrt(min_p d2)) over 24 clicks per (b,g) group,
// d2 = ((r-pr)/5)^2 + ((c-pc)/5)^2, invalid clicks (max coords < 0) -> 1e6.
// x input (d_in[0]) is shape-only; output depends only on coords (d_in[1]).
//
// FINAL (R13 confirmed): 4x128 window per warp, warp-granular click cull via
// ballot, tolerance-aware background (d2 >= 6.25 -> 1.0f, err = 1-tanh(5) =
// 9.1e-5, 10x inside the 1e-3 harness tolerance; interior computed exactly,
// measured rel_err 4.3e-5), 3-instr MUFU epilogue (sqrt.approx + tanh.approx),
// bit-packed output indexing, regs<=32 for a single 1024-CTA wave.
//
// Optimization history: duration proved invariant to instruction count (2x),
// warp count (2x), CTA shape (4x), occupancy (26->75%), store path (STG vs
// bulk TMA), wave count, and work clustering — all pipes <30% in every
// variant. The bench sits on a fixed floor (~8.6-8.7us) set by launch/replay
// overhead + effective store drain for the mandatory 16.8MB output.

namespace {

constexpr int   W         = 512;
constexpr int   P         = 24;      // clicks per group
constexpr float INV_SCALE = 0.2f;    // 1 / (NORM_RADIUS * SPATIAL_SCALE)
constexpr float CULL_D2   = 6.25f;   // 1 - tanh(2*sqrt(6.25)) = 9.1e-5

__device__ __forceinline__ float tanh_2sqrt_fast(float q) {
    float s, t;
    asm("sqrt.approx.f32 %0, %1;" : "=f"(s) : "f"(q));
    s = 2.0f * s;
    asm("tanh.approx.f32 %0, %1;" : "=f"(t) : "f"(s));
    return t;
}

__global__ __launch_bounds__(256, 8) void distmaps_kernel(
    const float* __restrict__ coords,   // [B, 48, 3] (row, col, _)
    float*       __restrict__ out)      // [B, 2, H, W]
{
    const int tid  = threadIdx.x;
    const int lane = tid & 31;
    const int bg   = blockIdx.y;                      // 0..2B-1

    const int wloc = (blockIdx.x << 3) + (tid >> 5);  // 0..511 window in group
    const int r0   = (wloc >> 2) << 2;                // window row base (4 rows)
    const int c0   = (wloc & 3) << 7;                 // window col base (128)

    // Lane p holds click p; test click against this warp's 4x128 window.
    float prs = 0.0f, pcs = 0.0f;
    bool  nearp = false;
    if (lane < P) {
        const float* cp = coords + (bg * P + lane) * 3;
        const float pr = __ldg(cp);
        const float pc = __ldg(cp + 1);
        const bool valid = fmaxf(pr, pc) >= 0.0f;     // invalid iff both < 0
        const float rr = fminf(fmaxf(pr, (float)r0), (float)(r0 + 3));
        const float cc = fminf(fmaxf(pc, (float)c0), (float)(c0 + 127));
        const float dr = (rr - pr) * INV_SCALE;
        const float dc = (cc - pc) * INV_SCALE;
        nearp = valid && (fmaf(dr, dr, dc * dc) < CULL_D2);
        prs = pr * INV_SCALE;
        pcs = pc * INV_SCALE;
    }
    unsigned mask = __ballot_sync(0xffffffffu, nearp);

    // Output index: bg<<18 | r0<<9 | c0 | lane<<2 (disjoint bit fields).
    const unsigned idx = ((unsigned)bg << 18) | ((unsigned)r0 << 9) |
                         (unsigned)(c0 | (lane << 2));
    float* obase = out + idx;

    if (mask == 0u) {
        // No click within reach: all pixels -> 1.0f (err <= 9.1e-5).
        const float4 ones = make_float4(1.0f, 1.0f, 1.0f, 1.0f);
#pragma unroll
        for (int i = 0; i < 4; ++i)
            *reinterpret_cast<float4*>(obase + i * W) = ones;
        return;
    }

    const float a0  = (float)(c0 | (lane << 2)) * INV_SCALE;
    const float rs0 = (float)r0 * INV_SCALE;

    float q[4][4];
#pragma unroll
    for (int i = 0; i < 4; ++i)
#pragma unroll
        for (int j = 0; j < 4; ++j) q[i][j] = CULL_D2;

    // Iterate surviving clicks (warp-uniform mask -> no divergence).
    while (mask) {
        const int p = __ffs(mask) - 1;
        mask &= mask - 1;
        const float pr = __shfl_sync(0xffffffffu, prs, p);
        const float pc = __shfl_sync(0xffffffffu, pcs, p);

        // Incremental column/row deltas keep the live set small (reg cap 32).
        const float dc0 = a0 - pc;
        const float dc1 = dc0 + INV_SCALE;
        const float dc2 = dc1 + INV_SCALE;
        const float dc3 = dc2 + INV_SCALE;
        float dr = rs0 - pr;
#pragma unroll
        for (int i = 0; i < 4; ++i) {
            const float e = dr * dr;
            q[i][0] = fminf(q[i][0], fmaf(dc0, dc0, e));
            q[i][1] = fminf(q[i][1], fmaf(dc1, dc1, e));
            q[i][2] = fminf(q[i][2], fmaf(dc2, dc2, e));
            q[i][3] = fminf(q[i][3], fmaf(dc3, dc3, e));
            dr += INV_SCALE;
        }
    }

    // Branchless epilogue (no vote): active warps always run MUFU.
#pragma unroll
    for (int i = 0; i < 4; ++i) {
        float4 v;
        v.x = tanh_2sqrt_fast(q[i][0]);
        v.y = tanh_2sqrt_fast(q[i][1]);
        v.z = tanh_2sqrt_fast(q[i][2]);
        v.w = tanh_2sqrt_fast(q[i][3]);
        *reinterpret_cast<float4*>(obase + i * W) = v;
    }
}

}  // namespace

extern "C" void kernel_launch(void* const* d_in, const int* in_sizes, int n_in,
                              void* d_out, int out_size) {
    // d_in[0]: x [B,3,512,512] f32 (unused), d_in[1]: coords [B,48,3] f32
    const float* coords = (const float*)d_in[1];
    float* out = (float*)d_out;

    const int B = in_sizes[1] / (48 * 3);   // 8
    dim3 grid(64, B * 2);                   // 1024 CTAs -> single wave @ 8/SM
    distmaps_kernel<<<grid, 256>>>(coords, out);
}